// round 4
// baseline (speedup 1.0000x reference)
#include <cuda_runtime.h>
#include <cuda_bf16.h>

// Forward-fill (LOCF) over x:(B=32, L=4096, N=256) fp32, NaN = missing.
// Single-pass chunked scan, decoupled lookback, stores overlapped with lookback.
//
//   chunk = 32 timesteps; grid = B*(L/32) = 4096 CTAs, 256 threads (thread = channel).
//   Values at/after the chunk's first observation are locally final -> stored
//   inside the load loop. Only the pre-first-obs prefix (E[len]~1.25) waits
//   for the carry and is patched afterward.
//
//   pub word (4B, per chunk*channel): 0x7fc00000 = unpublished (cleared),
//   0x7fc00001 = published-but-empty chunk, else = float bits of the chunk's
//   last observed value (data is finite, so never collides with NaN patterns).

#define BB 32
#define LL 4096
#define NN 256
#define LC 32
#define CC (LL / LC)          // 128 chunks per batch
#define NCHUNK (BB * CC)      // 4096 CTAs
#define NPUB (NCHUNK * NN)    // 1M words = 4 MB

#define PUB_CLEARED 0x7fc00000u
#define PUB_EMPTY   0x7fc00001u

__device__ unsigned g_pub[NPUB];

static __device__ __forceinline__ unsigned ld_cg_u32(const unsigned* p) {
    unsigned v;
    asm volatile("ld.global.cg.u32 %0, [%1];" : "=r"(v) : "l"(p) : "memory");
    return v;
}
static __device__ __forceinline__ void st_cg_u32(unsigned* p, unsigned v) {
    asm volatile("st.global.cg.u32 [%0], %1;" :: "l"(p), "r"(v) : "memory");
}

__global__ void __launch_bounds__(256) k_clear(void) {
    int t = blockIdx.x * blockDim.x + threadIdx.x;   // 1M/4 threads, uint4 each
    uint4 w = make_uint4(PUB_CLEARED, PUB_CLEARED, PUB_CLEARED, PUB_CLEARED);
    reinterpret_cast<uint4*>(g_pub)[t] = w;
}

template <bool WRITE_MASK>
__global__ void __launch_bounds__(256) k_locf(const float* __restrict__ x,
                                              float* __restrict__ out,
                                              float* __restrict__ outm) {
    const int n   = threadIdx.x;          // channel
    const int bid = blockIdx.x;           // (b, c)
    const int c   = bid % CC;
    const int b   = bid / CC;

    const size_t base = ((size_t)b * LL + (size_t)c * LC) * NN + n;

    // ---- streaming pass: load, scan, store everything that's locally final
    float run = __int_as_float(PUB_CLEARED);   // NaN sentinel: "no obs yet"
    int f = 0;                                  // # leading positions needing carry
    #pragma unroll
    for (int l = 0; l < LC; l++) {
        float v = __ldcs(x + base + (size_t)l * NN);
        bool valid = (v == v);
        run = valid ? v : run;
        if (run == run)
            __stcs(out + base + (size_t)l * NN, run);
        else
            f = l + 1;
        if (WRITE_MASK)
            __stcs(outm + base + (size_t)l * NN, valid ? 1.0f : 0.0f);
    }

    // ---- publish chunk aggregate (4B, self-contained)
    unsigned w = (run == run) ? __float_as_uint(run) : PUB_EMPTY;
    st_cg_u32(&g_pub[(size_t)bid * NN + n], w);

    // ---- lookback only if our prefix needs it
    if (f > 0) {
        float carry = 0.0f;
        if (c > 0) {
            int p = bid - 1;
            const int pmin = b * CC;
            while (p >= pmin) {
                unsigned pw = ld_cg_u32(&g_pub[(size_t)p * NN + n]);
                while (pw == PUB_CLEARED) {
                    __nanosleep(40);
                    pw = ld_cg_u32(&g_pub[(size_t)p * NN + n]);
                }
                if (pw != PUB_EMPTY) { carry = __uint_as_float(pw); break; }
                p--;                   // empty chunk (~never): keep walking
            }
        }
        // patch the unresolved prefix
        for (int l = 0; l < f; l++)
            __stcs(out + base + (size_t)l * NN, carry);
    }
}

extern "C" void kernel_launch(void* const* d_in, const int* in_sizes, int n_in,
                              void* d_out, int out_size) {
    const float* x = (const float*)d_in[0];
    long long total = (long long)in_sizes[0];   // 33554432
    float* out = (float*)d_out;

    k_clear<<<NPUB / (256 * 4), 256>>>();

    if ((long long)out_size >= 2 * total) {
        k_locf<true><<<NCHUNK, 256>>>(x, out, out + total);
    } else {
        k_locf<false><<<NCHUNK, 256>>>(x, out, nullptr);
    }
}

// round 5
// speedup vs baseline: 1.4150x; 1.4150x over previous
#include <cuda_runtime.h>
#include <cuda_bf16.h>

// Forward-fill (LOCF) over x:(B=32, L=4096, N=256) fp32, NaN = missing.
// Single-pass chunked scan + decoupled lookback.
//   chunk = 16 steps; grid = B*(L/16) = 8192 CTAs x 256 thr (thread = channel).
//   Phase 1: batch-load 16 steps into regs (MLP=16, coalesced 1KB/warp rows).
//   Phase 2: in-register scan; store run for ALL positions (prefix stores NaN,
//            patched later); publish chunk aggregate.
//   Phase 3: threads with an unresolved prefix (~20%) look back (~1 step) and
//            patch the prefix with the carry.
//
//   pub word (4B): 0x7fc00000 = unpublished, 0x7fc00001 = published-empty,
//   else float bits of chunk's last observation (data finite => unambiguous).

#define BB 32
#define LL 4096
#define NN 256
#define LC 16
#define CC (LL / LC)          // 256 chunks per batch
#define NCHUNK (BB * CC)      // 8192 CTAs
#define NPUB (NCHUNK * NN)    // 2M words = 8 MB

#define PUB_CLEARED 0x7fc00000u
#define PUB_EMPTY   0x7fc00001u

__device__ unsigned g_pub[NPUB];

static __device__ __forceinline__ unsigned ld_cg_u32(const unsigned* p) {
    unsigned v;
    asm volatile("ld.global.cg.u32 %0, [%1];" : "=r"(v) : "l"(p) : "memory");
    return v;
}
static __device__ __forceinline__ void st_cg_u32(unsigned* p, unsigned v) {
    asm volatile("st.global.cg.u32 [%0], %1;" :: "l"(p), "r"(v) : "memory");
}

__global__ void __launch_bounds__(256) k_clear(void) {
    int t = blockIdx.x * blockDim.x + threadIdx.x;   // NPUB/4 threads, uint4 each
    uint4 w = make_uint4(PUB_CLEARED, PUB_CLEARED, PUB_CLEARED, PUB_CLEARED);
    reinterpret_cast<uint4*>(g_pub)[t] = w;
}

template <bool WRITE_MASK>
__global__ void __launch_bounds__(256, 8) k_locf(const float* __restrict__ x,
                                                 float* __restrict__ out,
                                                 float* __restrict__ outm) {
    const int n   = threadIdx.x;          // channel
    const int bid = blockIdx.x;           // (b, c)
    const int c   = bid % CC;
    const int b   = bid / CC;

    const size_t base = ((size_t)b * LL + (size_t)c * LC) * NN + n;

    // ---- phase 1: front-batched loads (independent LDGs, MLP = 16)
    float v[LC];
    #pragma unroll
    for (int l = 0; l < LC; l++)
        v[l] = __ldcs(x + base + (size_t)l * NN);

    // ---- phase 2: in-register scan; store run (NaN for unresolved prefix)
    float run = __int_as_float(PUB_CLEARED);
    int f = 0;                            // # leading positions needing carry
    #pragma unroll
    for (int l = 0; l < LC; l++) {
        bool valid = (v[l] == v[l]);
        run = valid ? v[l] : run;
        f = (run == run) ? f : (l + 1);
        __stcs(out + base + (size_t)l * NN, run);
        if (WRITE_MASK)
            __stcs(outm + base + (size_t)l * NN, valid ? 1.0f : 0.0f);
    }

    // ---- publish chunk aggregate
    unsigned w = (run == run) ? __float_as_uint(run) : PUB_EMPTY;
    st_cg_u32(&g_pub[(size_t)bid * NN + n], w);

    // ---- phase 3: lookback + prefix patch (rare path, ~20% of threads)
    if (f > 0) {
        float carry = 0.0f;
        if (c > 0) {
            int p = bid - 1;
            const int pmin = b * CC;
            while (p >= pmin) {
                unsigned pw = ld_cg_u32(&g_pub[(size_t)p * NN + n]);
                while (pw == PUB_CLEARED) {
                    __nanosleep(40);
                    pw = ld_cg_u32(&g_pub[(size_t)p * NN + n]);
                }
                if (pw != PUB_EMPTY) { carry = __uint_as_float(pw); break; }
                p--;                       // empty chunk (~never)
            }
        }
        for (int l = 0; l < f; l++)
            __stcs(out + base + (size_t)l * NN, carry);
    }
}

extern "C" void kernel_launch(void* const* d_in, const int* in_sizes, int n_in,
                              void* d_out, int out_size) {
    const float* x = (const float*)d_in[0];
    long long total = (long long)in_sizes[0];   // 33554432
    float* out = (float*)d_out;

    k_clear<<<NPUB / (256 * 4), 256>>>();

    if ((long long)out_size >= 2 * total) {
        k_locf<true><<<NCHUNK, 256>>>(x, out, out + total);
    } else {
        k_locf<false><<<NCHUNK, 256>>>(x, out, nullptr);
    }
}